// round 12
// baseline (speedup 1.0000x reference)
#include <cuda_runtime.h>
#include <cuda_bf16.h>
#include <cuda_fp16.h>
#include <cstdint>
#include <math.h>

typedef unsigned int       u32;
typedef unsigned long long u64;

#define NN 100000
#define EE 300000
#define HIDD 128
#define NH (NN*HIDD)

// ---------------- static scratch (no allocations allowed) ----------------
__device__ float  g_h[3*NH];        // layer-1 GAT output (t,v,e) = layer-2 input
__device__ __half g_GLh[9*NH];      // per-relation src projections (fp16 to halve gather traffic)
__device__ float  g_GRa[9*NH];      // per-relation dst projections (fp32)
__device__ float  g_Wc[2*9*16*128]; // combined layer-1 weights  [side][rel][16][128]
__device__ float  g_brow[2*9*128];  // combined layer-1 bias rows
__device__ __half g_Whf[18*17408];  // layer-2 weights, padded fp16 images
__device__ int    g_off9[9*(NN+1)];
__device__ int    g_esrc9[9*EE];
__device__ int    g_cnt9[9*NN];
__device__ int    g_bsum9[9*128];

struct EI9 { const int* p[9]; };
struct X3  { const float* p[3]; };
struct WB3 { const float* W[3]; const float* b[3]; };

__device__ __constant__ int c_srct[9] = {0,0,1,0,2,1,2,1,2};
__device__ __constant__ int c_dstt[9] = {0,1,0,2,0,2,1,1,2};

// ================= baseline-PTX helpers =================
__device__ __forceinline__ u32 smem_u32(const void* p){
    u32 a;
    asm("{ .reg .u64 t; cvta.to.shared.u64 t, %1; cvt.u32.u64 %0, t; }" : "=r"(a) : "l"(p));
    return a;
}
__device__ __forceinline__ void ldsm4(u32* r, u32 addr){
    asm volatile("ldmatrix.sync.aligned.m8n8.x4.shared.b16 {%0,%1,%2,%3}, [%4];"
        : "=r"(r[0]),"=r"(r[1]),"=r"(r[2]),"=r"(r[3]) : "r"(addr));
}
__device__ __forceinline__ void ldsm2t(u32* r, u32 addr){
    asm volatile("ldmatrix.sync.aligned.m8n8.x2.trans.shared.b16 {%0,%1}, [%2];"
        : "=r"(r[0]),"=r"(r[1]) : "r"(addr));
}
__device__ __forceinline__ void mma16816(float* d, const u32* a, const u32* b){
    asm volatile(
        "mma.sync.aligned.m16n8k16.row.col.f32.bf16.bf16.f32 "
        "{%0,%1,%2,%3}, {%4,%5,%6,%7}, {%8,%9}, {%0,%1,%2,%3};"
        : "+f"(d[0]),"+f"(d[1]),"+f"(d[2]),"+f"(d[3])
        : "r"(a[0]),"r"(a[1]),"r"(a[2]),"r"(a[3]), "r"(b[0]),"r"(b[1]));
}
__device__ __forceinline__ void mma16816h(float* d, const u32* a, const u32* b){
    asm volatile(
        "mma.sync.aligned.m16n8k16.row.col.f32.f16.f16.f32 "
        "{%0,%1,%2,%3}, {%4,%5,%6,%7}, {%8,%9}, {%0,%1,%2,%3};"
        : "+f"(d[0]),"+f"(d[1]),"+f"(d[2]),"+f"(d[3])
        : "r"(a[0]),"r"(a[1]),"r"(a[2]),"r"(a[3]), "r"(b[0]),"r"(b[1]));
}
__device__ __forceinline__ void bf_split(float x, __nv_bfloat16& hi, __nv_bfloat16& lo){
    hi = __float2bfloat16(x);
    lo = __float2bfloat16(x - __bfloat162float(hi));
}
__device__ __forceinline__ void hf_split(float x, __half& hi, __half& lo){
    hi = __float2half(x);
    lo = __float2half(x - __half2float(hi));
}
__device__ __forceinline__ void cp16(u32 dst, const void* src){
    asm volatile("cp.async.cg.shared.global [%0], [%1], 16;" :: "r"(dst), "l"(src));
}

// ======== layer-2 GEMM smem layout (A fp16 hi/lo + double-buffered fp16 B) ========
#define LDE 136
#define PLANE 34816                 // 128*136*2 bytes
#define G_AHI 0
#define G_ALO PLANE
#define G_B(buf) (2*PLANE + (buf)*PLANE)
#define G_TOTAL (4*PLANE)           // 139264

// ======== layer-1 skinny GEMM smem layout (K=16, 6 weights, bf16 3-term) ========
#define LDA16 24
#define P_AHI 0
#define P_ALO (128*LDA16*2)                       // 6144
#define P_B(w)   (2*128*LDA16*2 + (w)*8704)
#define P_BLO(w) (P_B(w) + 4352)
#define P_BIAS   (2*128*LDA16*2 + 6*8704)         // 64512
#define P_TOTAL  (P_BIAS + 6*128*4)               // 67584

// ---------------- precompute combined layer-1 weights ----------------
__global__ void k_precomp(WB3 wb, const float* __restrict__ Wl1,
                          const float* __restrict__ Wr1,
                          float* __restrict__ Wc, float* __restrict__ brow){
    __shared__ float Ws[16*128];
    __shared__ float bs[128];
    const int rel  = blockIdx.x;
    const int side = blockIdx.y;
    const int ty   = side ? c_dstt[rel] : c_srct[rel];
    const float* Win = wb.W[ty];
    const float* bin = wb.b[ty];
    const float* WL  = (side ? Wr1 : Wl1) + (size_t)rel*16384;
    const int j = threadIdx.x;
    for (int i = j; i < 16*128; i += 128) Ws[i] = Win[i];
    bs[j] = bin[j];
    __syncthreads();
    float acc[16];
    #pragma unroll
    for (int i = 0; i < 16; i++) acc[i] = 0.f;
    float accb = 0.f;
    for (int k = 0; k < 128; k++){
        float wl = WL[k*128 + j];
        accb += bs[k]*wl;
        #pragma unroll
        for (int i = 0; i < 16; i++) acc[i] += Ws[i*128 + k]*wl;
    }
    float* Wcp = Wc + (size_t)(side*9 + rel)*2048;
    #pragma unroll
    for (int i = 0; i < 16; i++) Wcp[i*128 + j] = acc[i];
    brow[(side*9 + rel)*128 + j] = accb;
}

// ---------------- pre-convert layer-2 weights to padded fp16 images ----------
__global__ void k_wconv(const float* __restrict__ Wl, const float* __restrict__ Wr,
                        __half* __restrict__ out){
    const int rel  = blockIdx.x;
    const int side = blockIdx.y;
    const float* W = (side ? Wr : Wl) + (size_t)rel*16384;
    __half* base = out + (size_t)(side*9 + rel)*17408;
    for (int i = threadIdx.x; i < 16384; i += 256){
        int k = i >> 7, j = i & 127;
        base[k*LDE + j] = __float2half(W[i]);
    }
}

// ---------------- layer-1 projections: GL(fp16)/GR(fp32) = x @ Wc + brow ----------
__global__ __launch_bounds__(256, 1)
void k_p16(X3 xs, const float* __restrict__ Wc, const float* __restrict__ brow,
           __half* __restrict__ GLh, float* __restrict__ GRa){
    static const int srcR[3][3] = {{0,1,3},{2,5,7},{4,6,8}};
    static const int dstR[3][3] = {{0,2,4},{1,6,7},{3,5,8}};
    extern __shared__ char smem[];
    float* bias_s = (float*)(smem + P_BIAS);
    const u32 sb = smem_u32(smem);
    const int tid  = threadIdx.x;
    const int wid  = tid >> 5;
    const int lane = tid & 31;
    const int T    = blockIdx.y;

    if (tid < 128){
        int rg = blockIdx.x*128 + tid;
        if (rg > NN-1) rg = NN-1;
        const float4* xp = (const float4*)(xs.p[T] + (size_t)rg*16);
        #pragma unroll
        for (int jj = 0; jj < 4; jj++){
            float4 v = xp[jj];
            __nv_bfloat16 h0,h1,h2,h3,l0,l1,l2,l3;
            bf_split(v.x,h0,l0); bf_split(v.y,h1,l1);
            bf_split(v.z,h2,l2); bf_split(v.w,h3,l3);
            __nv_bfloat162 ph0; ph0.x=h0; ph0.y=h1;
            __nv_bfloat162 ph1; ph1.x=h2; ph1.y=h3;
            __nv_bfloat162 pl0; pl0.x=l0; pl0.y=l1;
            __nv_bfloat162 pl1; pl1.x=l2; pl1.y=l3;
            u32 o = (u32)(tid*LDA16 + jj*4)*2;
            *(__nv_bfloat162*)(smem + P_AHI + o)     = ph0;
            *(__nv_bfloat162*)(smem + P_AHI + o + 4) = ph1;
            *(__nv_bfloat162*)(smem + P_ALO + o)     = pl0;
            *(__nv_bfloat162*)(smem + P_ALO + o + 4) = pl1;
        }
    }
    for (int idx = tid; idx < 6*512; idx += 256){
        int w = idx >> 9, rem = idx & 511;
        int k = rem >> 5, j = (rem & 31) << 2;
        int side = (w < 3) ? 0 : 1;
        int rel  = (w < 3) ? srcR[T][w] : dstR[T][w-3];
        float4 v = *(const float4*)(Wc + (size_t)(side*9+rel)*2048 + k*128 + j);
        __nv_bfloat16 h0,h1,h2,h3,l0,l1,l2,l3;
        bf_split(v.x,h0,l0); bf_split(v.y,h1,l1);
        bf_split(v.z,h2,l2); bf_split(v.w,h3,l3);
        __nv_bfloat162 ph0; ph0.x=h0; ph0.y=h1;
        __nv_bfloat162 ph1; ph1.x=h2; ph1.y=h3;
        __nv_bfloat162 pl0; pl0.x=l0; pl0.y=l1;
        __nv_bfloat162 pl1; pl1.x=l2; pl1.y=l3;
        u32 o = (u32)(k*LDE + j)*2;
        *(__nv_bfloat162*)(smem + P_B(w) + o)       = ph0;
        *(__nv_bfloat162*)(smem + P_B(w) + o + 4)   = ph1;
        *(__nv_bfloat162*)(smem + P_BLO(w) + o)     = pl0;
        *(__nv_bfloat162*)(smem + P_BLO(w) + o + 4) = pl1;
    }
    for (int idx = tid; idx < 6*128; idx += 256){
        int w = idx >> 7, c = idx & 127;
        int side = (w < 3) ? 0 : 1;
        int rel  = (w < 3) ? srcR[T][w] : dstR[T][w-3];
        bias_s[idx] = brow[(side*9+rel)*128 + c];
    }
    __syncthreads();

    const int mg = (wid >> 1) * 32;
    const int ng = (wid & 1) * 64;
    const int arow = mg + (lane & 15);
    const int acol = (lane >> 4) << 3;
    const int brw  = lane & 15;

    u32 a_hi[2][4], a_lo[2][4];
    #pragma unroll
    for (int mt = 0; mt < 2; mt++){
        u32 ao = (u32)((arow + mt*16)*LDA16 + acol)*2;
        ldsm4(a_hi[mt], sb + P_AHI + ao);
        ldsm4(a_lo[mt], sb + P_ALO + ao);
    }

    const int r0 = blockIdx.x*128 + mg + (lane >> 2);
    const int c0 = ng + ((lane & 3) << 1);

    #pragma unroll
    for (int w = 0; w < 6; w++){
        int side = (w < 3) ? 0 : 1;
        int rel  = (w < 3) ? srcR[T][w] : dstR[T][w-3];
        float acc[2][8][4];
        #pragma unroll
        for (int mt = 0; mt < 2; mt++)
            #pragma unroll
            for (int nt = 0; nt < 8; nt++)
                #pragma unroll
                for (int q = 0; q < 4; q++) acc[mt][nt][q] = 0.f;
        #pragma unroll
        for (int nt = 0; nt < 8; nt++){
            u32 bo = (u32)(brw*LDE + ng + nt*8)*2;
            u32 b_hi[2], b_lo[2];
            ldsm2t(b_hi, sb + P_B(w) + bo);
            ldsm2t(b_lo, sb + P_BLO(w) + bo);
            #pragma unroll
            for (int mt = 0; mt < 2; mt++){
                mma16816(acc[mt][nt], a_hi[mt], b_hi);
                mma16816(acc[mt][nt], a_lo[mt], b_hi);
                mma16816(acc[mt][nt], a_hi[mt], b_lo);
            }
        }
        if (side){
            float* Cp = GRa + (size_t)rel*NH;
            #pragma unroll
            for (int mt = 0; mt < 2; mt++)
                #pragma unroll
                for (int nt = 0; nt < 8; nt++){
                    int ra = r0 + mt*16;
                    int cc = c0 + nt*8;
                    float b0 = bias_s[w*128 + cc];
                    float b1 = bias_s[w*128 + cc + 1];
                    if (ra < NN){
                        float2 v0; v0.x = acc[mt][nt][0] + b0; v0.y = acc[mt][nt][1] + b1;
                        *(float2*)(Cp + (size_t)ra*128 + cc) = v0;
                    }
                    if (ra + 8 < NN){
                        float2 v1; v1.x = acc[mt][nt][2] + b0; v1.y = acc[mt][nt][3] + b1;
                        *(float2*)(Cp + (size_t)(ra+8)*128 + cc) = v1;
                    }
                }
        } else {
            __half* Cp = GLh + (size_t)rel*NH;
            #pragma unroll
            for (int mt = 0; mt < 2; mt++)
                #pragma unroll
                for (int nt = 0; nt < 8; nt++){
                    int ra = r0 + mt*16;
                    int cc = c0 + nt*8;
                    float b0 = bias_s[w*128 + cc];
                    float b1 = bias_s[w*128 + cc + 1];
                    if (ra < NN)
                        *(__half2*)(Cp + (size_t)ra*128 + cc) =
                            __floats2half2_rn(acc[mt][nt][0] + b0, acc[mt][nt][1] + b1);
                    if (ra + 8 < NN)
                        *(__half2*)(Cp + (size_t)(ra+8)*128 + cc) =
                            __floats2half2_rn(acc[mt][nt][2] + b0, acc[mt][nt][3] + b1);
                }
        }
    }
}

// ========== layer-2 multi-W GEMM: fp16 2-term; GL out fp16, GR out fp32 ==========
__global__ __launch_bounds__(256, 1)
void k_gemm6(const float* __restrict__ hbase, const __half* __restrict__ Whf,
             __half* __restrict__ GLh, float* __restrict__ GRa){
    static const int srcR[3][3] = {{0,1,3},{2,5,7},{4,6,8}};
    static const int dstR[3][3] = {{0,2,4},{1,6,7},{3,5,8}};
    extern __shared__ char smem[];
    const u32 sb = smem_u32(smem);
    const int tid  = threadIdx.x;
    const int wid  = tid >> 5;
    const int lane = tid & 31;
    const int T    = blockIdx.y;
    const float* A = hbase + (size_t)T*NH;

    int rels[6];
    #pragma unroll
    for (int w = 0; w < 3; w++){ rels[w] = srcR[T][w]; rels[w+3] = dstR[T][w]; }

    auto copyW = [&](int w, int buf){
        int side = (w < 3) ? 0 : 1;
        const char* src = (const char*)(Whf + (size_t)(side*9 + rels[w])*17408);
        u32 dst = sb + G_B(buf);
        for (int i = tid*16; i < PLANE; i += 256*16)
            cp16(dst + i, src + i);
    };

    copyW(0, 0);
    asm volatile("cp.async.commit_group;" ::: "memory");

    for (int idx = tid; idx < 128*32; idx += 256){
        int r = idx >> 5, j = (idx & 31) << 2;
        int rg = blockIdx.x*128 + r;
        if (rg > NN-1) rg = NN-1;
        float4 v = *(const float4*)(A + (size_t)rg*128 + j);
        __half h0,h1,h2,h3,l0,l1,l2,l3;
        hf_split(v.x,h0,l0); hf_split(v.y,h1,l1);
        hf_split(v.z,h2,l2); hf_split(v.w,h3,l3);
        __half2 ph0; ph0.x=h0; ph0.y=h1;
        __half2 ph1; ph1.x=h2; ph1.y=h3;
        __half2 pl0; pl0.x=l0; pl0.y=l1;
        __half2 pl1; pl1.x=l2; pl1.y=l3;
        u32 o = (u32)(r*LDE + j)*2;
        *(__half2*)(smem + G_AHI + o)     = ph0;
        *(__half2*)(smem + G_AHI + o + 4) = ph1;
        *(__half2*)(smem + G_ALO + o)     = pl0;
        *(__half2*)(smem + G_ALO + o + 4) = pl1;
    }

    const int mg = (wid >> 1) * 32;
    const int ng = (wid & 1) * 64;
    const int arow = mg + (lane & 15);
    const int acol = (lane >> 4) << 3;
    const int brow = lane & 15;
    const int r0g = blockIdx.x*128 + mg + (lane >> 2);
    const int c0 = ng + ((lane & 3) << 1);

    for (int w = 0; w < 6; w++){
        if (w < 5){
            copyW(w+1, (w+1) & 1);
            asm volatile("cp.async.commit_group;" ::: "memory");
            asm volatile("cp.async.wait_group 1;" ::: "memory");
        } else {
            asm volatile("cp.async.wait_group 0;" ::: "memory");
        }
        __syncthreads();

        const u32 bhi = sb + G_B(w & 1);

        float acc[2][8][4];
        #pragma unroll
        for (int mt = 0; mt < 2; mt++)
            #pragma unroll
            for (int nt = 0; nt < 8; nt++)
                #pragma unroll
                for (int q = 0; q < 4; q++) acc[mt][nt][q] = 0.f;

        #pragma unroll
        for (int ks = 0; ks < 8; ks++){
            const int k0 = ks << 4;
            u32 a_hi[2][4], a_lo[2][4];
            #pragma unroll
            for (int mt = 0; mt < 2; mt++){
                u32 ao = (u32)((arow + mt*16)*LDE + k0 + acol)*2;
                ldsm4(a_hi[mt], sb + G_AHI + ao);
                ldsm4(a_lo[mt], sb + G_ALO + ao);
            }
            #pragma unroll
            for (int nt = 0; nt < 8; nt++){
                u32 bo = (u32)((k0 + brow)*LDE + ng + nt*8)*2;
                u32 b_hi[2];
                ldsm2t(b_hi, bhi + bo);
                #pragma unroll
                for (int mt = 0; mt < 2; mt++){
                    mma16816h(acc[mt][nt], a_hi[mt], b_hi);
                    mma16816h(acc[mt][nt], a_lo[mt], b_hi);
                }
            }
        }

        if (w < 3){
            __half* Cp = GLh + (size_t)rels[w]*NH;
            #pragma unroll
            for (int mt = 0; mt < 2; mt++)
                #pragma unroll
                for (int nt = 0; nt < 8; nt++){
                    int ra = r0g + mt*16;
                    int cc = c0 + nt*8;
                    if (ra < NN)
                        *(__half2*)(Cp + (size_t)ra*128 + cc) =
                            __floats2half2_rn(acc[mt][nt][0], acc[mt][nt][1]);
                    if (ra + 8 < NN)
                        *(__half2*)(Cp + (size_t)(ra+8)*128 + cc) =
                            __floats2half2_rn(acc[mt][nt][2], acc[mt][nt][3]);
                }
        } else {
            float* Cp = GRa + (size_t)rels[w]*NH;
            #pragma unroll
            for (int mt = 0; mt < 2; mt++)
                #pragma unroll
                for (int nt = 0; nt < 8; nt++){
                    int ra = r0g + mt*16;
                    int cc = c0 + nt*8;
                    if (ra < NN){
                        float2 v0; v0.x = acc[mt][nt][0]; v0.y = acc[mt][nt][1];
                        *(float2*)(Cp + (size_t)ra*128 + cc) = v0;
                    }
                    if (ra + 8 < NN){
                        float2 v1; v1.x = acc[mt][nt][2]; v1.y = acc[mt][nt][3];
                        *(float2*)(Cp + (size_t)(ra+8)*128 + cc) = v1;
                    }
                }
        }
        __syncthreads();
    }
}

// ---------------- batched CSR build ----------------
__global__ void k_zero(int* p, int n){
    int i = blockIdx.x*blockDim.x + threadIdx.x;
    if (i < n) p[i] = 0;
}
__global__ void k_hist9(EI9 ei, int* __restrict__ cnt9){
    int z = blockIdx.y;
    int e = blockIdx.x*blockDim.x + threadIdx.x;
    if (e < EE) atomicAdd(&cnt9[z*NN + ei.p[z][EE + e]], 1);
}
__global__ void k_scan1_9(int* __restrict__ cnt9, int* __restrict__ off9,
                          int* __restrict__ bsum9){
    __shared__ int sh[1024];
    int z = blockIdx.y;
    int d = blockIdx.x*1024 + threadIdx.x;
    sh[threadIdx.x] = (d < NN) ? cnt9[z*NN + d] : 0;
    if (d < NN) cnt9[z*NN + d] = 0;
    __syncthreads();
    for (int s = 1; s < 1024; s <<= 1){
        int t = (threadIdx.x >= s) ? sh[threadIdx.x - s] : 0;
        __syncthreads();
        sh[threadIdx.x] += t;
        __syncthreads();
    }
    if (d < NN) off9[z*(NN+1) + d + 1] = sh[threadIdx.x];
    if (threadIdx.x == 1023) bsum9[z*128 + blockIdx.x] = sh[1023];
}
__global__ void k_scan2_9(int* __restrict__ off9, const int* __restrict__ bsum9){
    __shared__ int pre;
    int z = blockIdx.y;
    if (threadIdx.x == 0){
        int s = 0;
        for (int b = 0; b < (int)blockIdx.x; b++) s += bsum9[z*128 + b];
        pre = s;
    }
    __syncthreads();
    int d = blockIdx.x*1024 + threadIdx.x;
    if (d < NN) off9[z*(NN+1) + d + 1] += pre;
    if (d == 0) off9[z*(NN+1)] = 0;
}
__global__ void k_fill9(EI9 ei, const int* __restrict__ off9,
                        int* __restrict__ cnt9, int* __restrict__ esrc9){
    int z = blockIdx.y;
    int e = blockIdx.x*blockDim.x + threadIdx.x;
    if (e < EE){
        int d = ei.p[z][EE + e];
        int pos = off9[z*(NN+1) + d] + atomicAdd(&cnt9[z*NN + d], 1);
        esrc9[z*EE + pos] = ei.p[z][e];
    }
}

// ---------------- fused GATv2: fp16 GL gathers, depth-2 prefetch ----------
__global__ __launch_bounds__(256)
void k_gat3(const int* __restrict__ off9, const int* __restrict__ esrc9,
            const __half* __restrict__ GLh, const float* __restrict__ GRa,
            const float* __restrict__ att, const float* __restrict__ bc,
            float* __restrict__ out, int r0, int r1, int r2, int dorelu){
    int d    = (blockIdx.x*blockDim.x + threadIdx.x) >> 5;
    int lane = threadIdx.x & 31;
    if (d >= NN) return;
    const int c = lane*4;

    float4 res;
    {
        float4 b0 = *(const float4*)&bc[r0*128 + c];
        float4 b1 = *(const float4*)&bc[r1*128 + c];
        float4 b2 = *(const float4*)&bc[r2*128 + c];
        res.x = b0.x + b1.x + b2.x;
        res.y = b0.y + b1.y + b2.y;
        res.z = b0.z + b1.z + b2.z;
        res.w = b0.w + b1.w + b2.w;
    }

    int rels[3]; rels[0] = r0; rels[1] = r1; rels[2] = r2;
    #pragma unroll
    for (int i = 0; i < 3; i++){
        const int r = rels[i];
        const int* off = off9 + r*(NN+1);
        const int* es  = esrc9 + (size_t)r*EE;
        const __half* GL = GLh + (size_t)r*NH;
        float4 gr = *(const float4*)&GRa[(size_t)r*NH + (size_t)d*128 + c];
        float4 at = *(const float4*)&att[r*128 + c];
        int beg = off[d], end = off[d+1];
        float m = -INFINITY, den = 0.f;
        float4 acc = make_float4(0.f,0.f,0.f,0.f);
        if (beg < end){
            int s0 = es[beg];
            uint2 u = *(const uint2*)&GL[(size_t)s0*128 + c];
            for (int k = beg; k < end; k++){
                // prefetch next edge's gather (depth-2 pipeline; order preserved)
                int kn = (k + 1 < end) ? (k + 1) : k;
                int sn = es[kn];
                uint2 un = *(const uint2*)&GL[(size_t)sn*128 + c];

                float2 f0 = __half22float2(*reinterpret_cast<__half2*>(&u.x));
                float2 f1 = __half22float2(*reinterpret_cast<__half2*>(&u.y));
                float4 gl; gl.x = f0.x; gl.y = f0.y; gl.z = f1.x; gl.w = f1.y;

                float sx = gl.x + gr.x, sy = gl.y + gr.y, sz = gl.z + gr.z, sw = gl.w + gr.w;
                sx = sx > 0.f ? sx : 0.2f*sx;
                sy = sy > 0.f ? sy : 0.2f*sy;
                sz = sz > 0.f ? sz : 0.2f*sz;
                sw = sw > 0.f ? sw : 0.2f*sw;
                float e = at.x*sx + at.y*sy + at.z*sz + at.w*sw;
                e += __shfl_xor_sync(0xffffffffu, e, 1);
                e += __shfl_xor_sync(0xffffffffu, e, 2);
                e += __shfl_xor_sync(0xffffffffu, e, 4);
                e += __shfl_xor_sync(0xffffffffu, e, 8);   // per-head score per half-warp
                float mn = fmaxf(m, e);
                float cs = __expf(m - mn);
                float p  = __expf(e - mn);
                den = den*cs + p;
                acc.x = acc.x*cs + p*gl.x;
                acc.y = acc.y*cs + p*gl.y;
                acc.z = acc.z*cs + p*gl.z;
                acc.w = acc.w*cs + p*gl.w;
                m = mn;
                u = un;
            }
        }
        float inv = 1.f / (den + 1e-16f);
        res.x += acc.x*inv;
        res.y += acc.y*inv;
        res.z += acc.z*inv;
        res.w += acc.w*inv;
    }
    if (dorelu){
        res.x = fmaxf(res.x, 0.f); res.y = fmaxf(res.y, 0.f);
        res.z = fmaxf(res.z, 0.f); res.w = fmaxf(res.w, 0.f);
    }
    *(float4*)&out[(size_t)d*128 + c] = res;
}

// ---------------- launch ----------------
extern "C" void kernel_launch(void* const* d_in, const int* in_sizes, int n_in,
                              void* d_out, int out_size){
    float *h, *GRa, *Wc, *brow;
    __half *GLh, *Whf;
    int *off9, *esrc9, *cnt9, *bsum9;
    cudaGetSymbolAddress((void**)&h,     g_h);
    cudaGetSymbolAddress((void**)&GLh,   g_GLh);
    cudaGetSymbolAddress((void**)&GRa,   g_GRa);
    cudaGetSymbolAddress((void**)&Wc,    g_Wc);
    cudaGetSymbolAddress((void**)&brow,  g_brow);
    cudaGetSymbolAddress((void**)&Whf,   g_Whf);
    cudaGetSymbolAddress((void**)&off9,  g_off9);
    cudaGetSymbolAddress((void**)&esrc9, g_esrc9);
    cudaGetSymbolAddress((void**)&cnt9,  g_cnt9);
    cudaGetSymbolAddress((void**)&bsum9, g_bsum9);

    cudaFuncSetAttribute(k_gemm6, cudaFuncAttributeMaxDynamicSharedMemorySize, G_TOTAL);
    cudaFuncSetAttribute(k_p16,   cudaFuncAttributeMaxDynamicSharedMemorySize, P_TOTAL);

    EI9 ei;
    for (int r = 0; r < 9; r++) ei.p[r] = (const int*)d_in[3 + r];
    X3 xs;
    xs.p[0] = (const float*)d_in[0];
    xs.p[1] = (const float*)d_in[1];
    xs.p[2] = (const float*)d_in[2];
    WB3 wb;
    wb.W[0] = (const float*)d_in[12]; wb.b[0] = (const float*)d_in[13];
    wb.W[1] = (const float*)d_in[14]; wb.b[1] = (const float*)d_in[15];
    wb.W[2] = (const float*)d_in[16]; wb.b[2] = (const float*)d_in[17];

    static const int dstR[3][3] = {{0,2,4},{1,6,7},{3,5,8}};
    const int gblk = (NN + 127) / 128;
    float* outF = (float*)d_out;

    // CSR build + layer-1 projections + weight pre-conversion
    k_zero<<<(9*NN + 255)/256, 256>>>(cnt9, 9*NN);
    { dim3 g((EE+255)/256, 9);   k_hist9  <<<g, 256>>> (ei, cnt9); }
    { dim3 g(9, 2); k_precomp<<<g, 128>>>(wb, (const float*)d_in[18], (const float*)d_in[19], Wc, brow); }
    { dim3 g(9, 2); k_wconv  <<<g, 256>>>((const float*)d_in[22], (const float*)d_in[23], Whf); }
    { dim3 g(gblk, 3); k_p16<<<g, 256, P_TOTAL>>>(xs, Wc, brow, GLh, GRa); }
    { dim3 g((NN+1023)/1024, 9); k_scan1_9<<<g, 1024>>>(cnt9, off9, bsum9); }
    { dim3 g((NN+1023)/1024, 9); k_scan2_9<<<g, 1024>>>(off9, bsum9); }
    { dim3 g((EE+255)/256, 9);   k_fill9  <<<g, 256>>> (ei, off9, cnt9, esrc9); }
    // layer-1 GAT (+bias +relu) -> h
    for (int T = 0; T < 3; T++){
        k_gat3<<<NN/8, 256>>>(off9, esrc9, GLh, GRa,
                              (const float*)d_in[20], (const float*)d_in[21],
                              h + (size_t)T*NH, dstR[T][0], dstR[T][1], dstR[T][2], 1);
    }
    // layer-2 projections (fp16 2-term, cp.async double-buffered)
    { dim3 g(gblk, 3); k_gemm6<<<g, 256, G_TOTAL>>>(h, Whf, GLh, GRa); }
    // layer-2 GAT (+bias) -> output
    for (int T = 0; T < 3; T++){
        k_gat3<<<NN/8, 256>>>(off9, esrc9, GLh, GRa,
                              (const float*)d_in[24], (const float*)d_in[25],
                              outF + (size_t)T*NH, dstR[T][0], dstR[T][1], dstR[T][2], 0);
    }
}

// round 13
// speedup vs baseline: 1.3690x; 1.3690x over previous
#include <cuda_runtime.h>
#include <cuda_bf16.h>
#include <cuda_fp16.h>
#include <cstdint>
#include <math.h>

typedef unsigned int       u32;
typedef unsigned long long u64;

#define NN 100000
#define EE 300000
#define HIDD 128
#define NH (NN*HIDD)

// ---------------- static scratch (no allocations allowed) ----------------
__device__ float  g_h[3*NH];        // layer-1 GAT output (t,v,e) = layer-2 input
__device__ float  g_GLa[9*NH];      // per-relation src projections
__device__ float  g_GRa[9*NH];      // per-relation dst projections
__device__ float  g_Wc[2*9*16*128]; // combined layer-1 weights  [side][rel][16][128]
__device__ float  g_brow[2*9*128];  // combined layer-1 bias rows
__device__ __half g_Whf[18*17408];  // layer-2 weights, padded fp16 images
__device__ int    g_off9[9*(NN+1)];
__device__ int    g_esrc9[9*EE];
__device__ int    g_cnt9[9*NN];
__device__ int    g_bsum9[9*128];

struct EI9 { const int* p[9]; };
struct X3  { const float* p[3]; };
struct WB3 { const float* W[3]; const float* b[3]; };

__device__ __constant__ int c_srct[9] = {0,0,1,0,2,1,2,1,2};
__device__ __constant__ int c_dstt[9] = {0,1,0,2,0,2,1,1,2};
__device__ __constant__ int c_dstR[3][3] = {{0,2,4},{1,6,7},{3,5,8}};

// ================= baseline-PTX helpers =================
__device__ __forceinline__ u32 smem_u32(const void* p){
    u32 a;
    asm("{ .reg .u64 t; cvta.to.shared.u64 t, %1; cvt.u32.u64 %0, t; }" : "=r"(a) : "l"(p));
    return a;
}
__device__ __forceinline__ void ldsm4(u32* r, u32 addr){
    asm volatile("ldmatrix.sync.aligned.m8n8.x4.shared.b16 {%0,%1,%2,%3}, [%4];"
        : "=r"(r[0]),"=r"(r[1]),"=r"(r[2]),"=r"(r[3]) : "r"(addr));
}
__device__ __forceinline__ void ldsm2t(u32* r, u32 addr){
    asm volatile("ldmatrix.sync.aligned.m8n8.x2.trans.shared.b16 {%0,%1}, [%2];"
        : "=r"(r[0]),"=r"(r[1]) : "r"(addr));
}
__device__ __forceinline__ void mma16816(float* d, const u32* a, const u32* b){
    asm volatile(
        "mma.sync.aligned.m16n8k16.row.col.f32.bf16.bf16.f32 "
        "{%0,%1,%2,%3}, {%4,%5,%6,%7}, {%8,%9}, {%0,%1,%2,%3};"
        : "+f"(d[0]),"+f"(d[1]),"+f"(d[2]),"+f"(d[3])
        : "r"(a[0]),"r"(a[1]),"r"(a[2]),"r"(a[3]), "r"(b[0]),"r"(b[1]));
}
__device__ __forceinline__ void mma16816h(float* d, const u32* a, const u32* b){
    asm volatile(
        "mma.sync.aligned.m16n8k16.row.col.f32.f16.f16.f32 "
        "{%0,%1,%2,%3}, {%4,%5,%6,%7}, {%8,%9}, {%0,%1,%2,%3};"
        : "+f"(d[0]),"+f"(d[1]),"+f"(d[2]),"+f"(d[3])
        : "r"(a[0]),"r"(a[1]),"r"(a[2]),"r"(a[3]), "r"(b[0]),"r"(b[1]));
}
__device__ __forceinline__ void bf_split(float x, __nv_bfloat16& hi, __nv_bfloat16& lo){
    hi = __float2bfloat16(x);
    lo = __float2bfloat16(x - __bfloat162float(hi));
}
__device__ __forceinline__ void hf_split(float x, __half& hi, __half& lo){
    hi = __float2half(x);
    lo = __float2half(x - __half2float(hi));
}
__device__ __forceinline__ void cp16(u32 dst, const void* src){
    asm volatile("cp.async.cg.shared.global [%0], [%1], 16;" :: "r"(dst), "l"(src));
}

// ======== layer-2 GEMM smem layout (A fp16 hi/lo + single fp16 B buffer -> occ 2) ========
#define LDE 136
#define PLANE 34816                 // 128*136*2 bytes
#define G_AHI 0
#define G_ALO PLANE
#define G_BB  (2*PLANE)
#define G_TOTAL (3*PLANE)           // 104448 -> 2 CTAs/SM

// ======== layer-1 skinny GEMM smem layout (K=16, 6 weights, bf16 3-term) ========
#define LDA16 24
#define P_AHI 0
#define P_ALO (128*LDA16*2)                       // 6144
#define P_B(w)   (2*128*LDA16*2 + (w)*8704)
#define P_BLO(w) (P_B(w) + 4352)
#define P_BIAS   (2*128*LDA16*2 + 6*8704)         // 64512
#define P_TOTAL  (P_BIAS + 6*128*4)               // 67584

// ---------------- precompute combined layer-1 weights ----------------
__global__ void k_precomp(WB3 wb, const float* __restrict__ Wl1,
                          const float* __restrict__ Wr1,
                          float* __restrict__ Wc, float* __restrict__ brow){
    __shared__ float Ws[16*128];
    __shared__ float bs[128];
    const int rel  = blockIdx.x;
    const int side = blockIdx.y;
    const int ty   = side ? c_dstt[rel] : c_srct[rel];
    const float* Win = wb.W[ty];
    const float* bin = wb.b[ty];
    const float* WL  = (side ? Wr1 : Wl1) + (size_t)rel*16384;
    const int j = threadIdx.x;
    for (int i = j; i < 16*128; i += 128) Ws[i] = Win[i];
    bs[j] = bin[j];
    __syncthreads();
    float acc[16];
    #pragma unroll
    for (int i = 0; i < 16; i++) acc[i] = 0.f;
    float accb = 0.f;
    for (int k = 0; k < 128; k++){
        float wl = WL[k*128 + j];
        accb += bs[k]*wl;
        #pragma unroll
        for (int i = 0; i < 16; i++) acc[i] += Ws[i*128 + k]*wl;
    }
    float* Wcp = Wc + (size_t)(side*9 + rel)*2048;
    #pragma unroll
    for (int i = 0; i < 16; i++) Wcp[i*128 + j] = acc[i];
    brow[(side*9 + rel)*128 + j] = accb;
}

// ---------------- pre-convert layer-2 weights to padded fp16 images ----------
__global__ void k_wconv(const float* __restrict__ Wl, const float* __restrict__ Wr,
                        __half* __restrict__ out){
    const int rel  = blockIdx.x;
    const int side = blockIdx.y;
    const float* W = (side ? Wr : Wl) + (size_t)rel*16384;
    __half* base = out + (size_t)(side*9 + rel)*17408;
    for (int i = threadIdx.x; i < 16384; i += 256){
        int k = i >> 7, j = i & 127;
        base[k*LDE + j] = __float2half(W[i]);
    }
}

// ---------------- layer-1 projections: GL/GR = x[1e5,16] @ Wc[16,128] + brow ----------
__global__ __launch_bounds__(256, 1)
void k_p16(X3 xs, const float* __restrict__ Wc, const float* __restrict__ brow,
           float* __restrict__ GLa, float* __restrict__ GRa){
    static const int srcR[3][3] = {{0,1,3},{2,5,7},{4,6,8}};
    static const int dstR[3][3] = {{0,2,4},{1,6,7},{3,5,8}};
    extern __shared__ char smem[];
    float* bias_s = (float*)(smem + P_BIAS);
    const u32 sb = smem_u32(smem);
    const int tid  = threadIdx.x;
    const int wid  = tid >> 5;
    const int lane = tid & 31;
    const int T    = blockIdx.y;

    if (tid < 128){
        int rg = blockIdx.x*128 + tid;
        if (rg > NN-1) rg = NN-1;
        const float4* xp = (const float4*)(xs.p[T] + (size_t)rg*16);
        #pragma unroll
        for (int jj = 0; jj < 4; jj++){
            float4 v = xp[jj];
            __nv_bfloat16 h0,h1,h2,h3,l0,l1,l2,l3;
            bf_split(v.x,h0,l0); bf_split(v.y,h1,l1);
            bf_split(v.z,h2,l2); bf_split(v.w,h3,l3);
            __nv_bfloat162 ph0; ph0.x=h0; ph0.y=h1;
            __nv_bfloat162 ph1; ph1.x=h2; ph1.y=h3;
            __nv_bfloat162 pl0; pl0.x=l0; pl0.y=l1;
            __nv_bfloat162 pl1; pl1.x=l2; pl1.y=l3;
            u32 o = (u32)(tid*LDA16 + jj*4)*2;
            *(__nv_bfloat162*)(smem + P_AHI + o)     = ph0;
            *(__nv_bfloat162*)(smem + P_AHI + o + 4) = ph1;
            *(__nv_bfloat162*)(smem + P_ALO + o)     = pl0;
            *(__nv_bfloat162*)(smem + P_ALO + o + 4) = pl1;
        }
    }
    for (int idx = tid; idx < 6*512; idx += 256){
        int w = idx >> 9, rem = idx & 511;
        int k = rem >> 5, j = (rem & 31) << 2;
        int side = (w < 3) ? 0 : 1;
        int rel  = (w < 3) ? srcR[T][w] : dstR[T][w-3];
        float4 v = *(const float4*)(Wc + (size_t)(side*9+rel)*2048 + k*128 + j);
        __nv_bfloat16 h0,h1,h2,h3,l0,l1,l2,l3;
        bf_split(v.x,h0,l0); bf_split(v.y,h1,l1);
        bf_split(v.z,h2,l2); bf_split(v.w,h3,l3);
        __nv_bfloat162 ph0; ph0.x=h0; ph0.y=h1;
        __nv_bfloat162 ph1; ph1.x=h2; ph1.y=h3;
        __nv_bfloat162 pl0; pl0.x=l0; pl0.y=l1;
        __nv_bfloat162 pl1; pl1.x=l2; pl1.y=l3;
        u32 o = (u32)(k*LDE + j)*2;
        *(__nv_bfloat162*)(smem + P_B(w) + o)       = ph0;
        *(__nv_bfloat162*)(smem + P_B(w) + o + 4)   = ph1;
        *(__nv_bfloat162*)(smem + P_BLO(w) + o)     = pl0;
        *(__nv_bfloat162*)(smem + P_BLO(w) + o + 4) = pl1;
    }
    for (int idx = tid; idx < 6*128; idx += 256){
        int w = idx >> 7, c = idx & 127;
        int side = (w < 3) ? 0 : 1;
        int rel  = (w < 3) ? srcR[T][w] : dstR[T][w-3];
        bias_s[idx] = brow[(side*9+rel)*128 + c];
    }
    __syncthreads();

    const int mg = (wid >> 1) * 32;
    const int ng = (wid & 1) * 64;
    const int arow = mg + (lane & 15);
    const int acol = (lane >> 4) << 3;
    const int brw  = lane & 15;

    u32 a_hi[2][4], a_lo[2][4];
    #pragma unroll
    for (int mt = 0; mt < 2; mt++){
        u32 ao = (u32)((arow + mt*16)*LDA16 + acol)*2;
        ldsm4(a_hi[mt], sb + P_AHI + ao);
        ldsm4(a_lo[mt], sb + P_ALO + ao);
    }

    const int r0 = blockIdx.x*128 + mg + (lane >> 2);
    const int c0 = ng + ((lane & 3) << 1);

    #pragma unroll
    for (int w = 0; w < 6; w++){
        int side = (w < 3) ? 0 : 1;
        int rel  = (w < 3) ? srcR[T][w] : dstR[T][w-3];
        float* Cp = (side ? GRa : GLa) + (size_t)rel*NH;
        float acc[2][8][4];
        #pragma unroll
        for (int mt = 0; mt < 2; mt++)
            #pragma unroll
            for (int nt = 0; nt < 8; nt++)
                #pragma unroll
                for (int q = 0; q < 4; q++) acc[mt][nt][q] = 0.f;
        #pragma unroll
        for (int nt = 0; nt < 8; nt++){
            u32 bo = (u32)(brw*LDE + ng + nt*8)*2;
            u32 b_hi[2], b_lo[2];
            ldsm2t(b_hi, sb + P_B(w) + bo);
            ldsm2t(b_lo, sb + P_BLO(w) + bo);
            #pragma unroll
            for (int mt = 0; mt < 2; mt++){
                mma16816(acc[mt][nt], a_hi[mt], b_hi);
                mma16816(acc[mt][nt], a_lo[mt], b_hi);
                mma16816(acc[mt][nt], a_hi[mt], b_lo);
            }
        }
        #pragma unroll
        for (int mt = 0; mt < 2; mt++){
            #pragma unroll
            for (int nt = 0; nt < 8; nt++){
                int ra = r0 + mt*16;
                int cc = c0 + nt*8;
                float b0 = bias_s[w*128 + cc];
                float b1 = bias_s[w*128 + cc + 1];
                if (ra < NN){
                    float2 v0; v0.x = acc[mt][nt][0] + b0; v0.y = acc[mt][nt][1] + b1;
                    *(float2*)(Cp + (size_t)ra*128 + cc) = v0;
                }
                if (ra + 8 < NN){
                    float2 v1; v1.x = acc[mt][nt][2] + b0; v1.y = acc[mt][nt][3] + b1;
                    *(float2*)(Cp + (size_t)(ra+8)*128 + cc) = v1;
                }
            }
        }
    }
}

// ========== layer-2 multi-W GEMM: fp16 2-term, single B buffer, occ 2 ==========
__global__ __launch_bounds__(256, 2)
void k_gemm6(const float* __restrict__ hbase, const __half* __restrict__ Whf,
             float* __restrict__ GLa, float* __restrict__ GRa){
    static const int srcR[3][3] = {{0,1,3},{2,5,7},{4,6,8}};
    static const int dstR[3][3] = {{0,2,4},{1,6,7},{3,5,8}};
    extern __shared__ char smem[];
    const u32 sb = smem_u32(smem);
    const int tid  = threadIdx.x;
    const int wid  = tid >> 5;
    const int lane = tid & 31;
    const int T    = blockIdx.y;
    const float* A = hbase + (size_t)T*NH;

    int rels[6];
    #pragma unroll
    for (int w = 0; w < 3; w++){ rels[w] = srcR[T][w]; rels[w+3] = dstR[T][w]; }

    auto copyW = [&](int w){
        int side = (w < 3) ? 0 : 1;
        const char* src = (const char*)(Whf + (size_t)(side*9 + rels[w])*17408);
        u32 dst = sb + G_BB;
        for (int i = tid*16; i < PLANE; i += 256*16)
            cp16(dst + i, src + i);
    };

    copyW(0);
    asm volatile("cp.async.commit_group;" ::: "memory");

    // ---- A tile fp16 hi/lo, converted once, reused by all 6 weights ----
    for (int idx = tid; idx < 128*32; idx += 256){
        int r = idx >> 5, j = (idx & 31) << 2;
        int rg = blockIdx.x*128 + r;
        if (rg > NN-1) rg = NN-1;
        float4 v = *(const float4*)(A + (size_t)rg*128 + j);
        __half h0,h1,h2,h3,l0,l1,l2,l3;
        hf_split(v.x,h0,l0); hf_split(v.y,h1,l1);
        hf_split(v.z,h2,l2); hf_split(v.w,h3,l3);
        __half2 ph0; ph0.x=h0; ph0.y=h1;
        __half2 ph1; ph1.x=h2; ph1.y=h3;
        __half2 pl0; pl0.x=l0; pl0.y=l1;
        __half2 pl1; pl1.x=l2; pl1.y=l3;
        u32 o = (u32)(r*LDE + j)*2;
        *(__half2*)(smem + G_AHI + o)     = ph0;
        *(__half2*)(smem + G_AHI + o + 4) = ph1;
        *(__half2*)(smem + G_ALO + o)     = pl0;
        *(__half2*)(smem + G_ALO + o + 4) = pl1;
    }

    const int mg = (wid >> 1) * 32;
    const int ng = (wid & 1) * 64;
    const int arow = mg + (lane & 15);
    const int acol = (lane >> 4) << 3;
    const int brow = lane & 15;
    const int r0g = blockIdx.x*128 + mg + (lane >> 2);
    const int c0 = ng + ((lane & 3) << 1);

    for (int w = 0; w < 6; w++){
        if (w > 0){
            copyW(w);       // safe: prior compute synced below before overwrite
            asm volatile("cp.async.commit_group;" ::: "memory");
        }
        asm volatile("cp.async.wait_group 0;" ::: "memory");
        __syncthreads();    // B ready for all warps (and A visible on first iter)

        const u32 bhi = sb + G_BB;
        float* Cp = ((w < 3) ? GLa : GRa) + (size_t)rels[w]*NH;

        float acc[2][8][4];
        #pragma unroll
        for (int mt = 0; mt < 2; mt++)
            #pragma unroll
            for (int nt = 0; nt < 8; nt++)
                #pragma unroll
                for (int q = 0; q < 4; q++) acc[mt][nt][q] = 0.f;

        #pragma unroll
        for (int ks = 0; ks < 8; ks++){
            const int k0 = ks << 4;
            u32 a_hi[2][4], a_lo[2][4];
            #pragma unroll
            for (int mt = 0; mt < 2; mt++){
                u32 ao = (u32)((arow + mt*16)*LDE + k0 + acol)*2;
                ldsm4(a_hi[mt], sb + G_AHI + ao);
                ldsm4(a_lo[mt], sb + G_ALO + ao);
            }
            #pragma unroll
            for (int nt = 0; nt < 8; nt++){
                u32 bo = (u32)((k0 + brow)*LDE + ng + nt*8)*2;
                u32 b_hi[2];
                ldsm2t(b_hi, bhi + bo);
                #pragma unroll
                for (int mt = 0; mt < 2; mt++){
                    mma16816h(acc[mt][nt], a_hi[mt], b_hi);
                    mma16816h(acc[mt][nt], a_lo[mt], b_hi);
                }
            }
        }

        #pragma unroll
        for (int mt = 0; mt < 2; mt++){
            #pragma unroll
            for (int nt = 0; nt < 8; nt++){
                int ra = r0g + mt*16;
                int cc = c0 + nt*8;
                if (ra < NN){
                    float2 v0; v0.x = acc[mt][nt][0]; v0.y = acc[mt][nt][1];
                    *(float2*)(Cp + (size_t)ra*128 + cc) = v0;
                }
                if (ra + 8 < NN){
                    float2 v1; v1.x = acc[mt][nt][2]; v1.y = acc[mt][nt][3];
                    *(float2*)(Cp + (size_t)(ra+8)*128 + cc) = v1;
                }
            }
        }
        __syncthreads();   // all warps done reading B before next copy overwrites it
    }
}

// ---------------- batched CSR build ----------------
__global__ void k_zero(int* p, int n){
    int i = blockIdx.x*blockDim.x + threadIdx.x;
    if (i < n) p[i] = 0;
}
__global__ void k_hist9(EI9 ei, int* __restrict__ cnt9){
    int z = blockIdx.y;
    int e = blockIdx.x*blockDim.x + threadIdx.x;
    if (e < EE) atomicAdd(&cnt9[z*NN + ei.p[z][EE + e]], 1);
}
__global__ void k_scan1_9(int* __restrict__ cnt9, int* __restrict__ off9,
                          int* __restrict__ bsum9){
    __shared__ int sh[1024];
    int z = blockIdx.y;
    int d = blockIdx.x*1024 + threadIdx.x;
    sh[threadIdx.x] = (d < NN) ? cnt9[z*NN + d] : 0;
    if (d < NN) cnt9[z*NN + d] = 0;
    __syncthreads();
    for (int s = 1; s < 1024; s <<= 1){
        int t = (threadIdx.x >= s) ? sh[threadIdx.x - s] : 0;
        __syncthreads();
        sh[threadIdx.x] += t;
        __syncthreads();
    }
    if (d < NN) off9[z*(NN+1) + d + 1] = sh[threadIdx.x];
    if (threadIdx.x == 1023) bsum9[z*128 + blockIdx.x] = sh[1023];
}
__global__ void k_scan2_9(int* __restrict__ off9, const int* __restrict__ bsum9){
    __shared__ int pre;
    int z = blockIdx.y;
    if (threadIdx.x == 0){
        int s = 0;
        for (int b = 0; b < (int)blockIdx.x; b++) s += bsum9[z*128 + b];
        pre = s;
    }
    __syncthreads();
    int d = blockIdx.x*1024 + threadIdx.x;
    if (d < NN) off9[z*(NN+1) + d + 1] += pre;
    if (d == 0) off9[z*(NN+1)] = 0;
}
__global__ void k_fill9(EI9 ei, const int* __restrict__ off9,
                        int* __restrict__ cnt9, int* __restrict__ esrc9){
    int z = blockIdx.y;
    int e = blockIdx.x*blockDim.x + threadIdx.x;
    if (e < EE){
        int d = ei.p[z][EE + e];
        int pos = off9[z*(NN+1) + d] + atomicAdd(&cnt9[z*NN + d], 1);
        esrc9[z*EE + pos] = ei.p[z][e];
    }
}

// ---------------- fused GATv2: grid.y = dst type, depth-2 prefetch ----------
__global__ __launch_bounds__(256)
void k_gat3(const int* __restrict__ off9, const int* __restrict__ esrc9,
            const float* __restrict__ GLa, const float* __restrict__ GRa,
            const float* __restrict__ att, const float* __restrict__ bc,
            float* __restrict__ out_base, int dorelu){
    const int T = blockIdx.y;
    const int r0 = c_dstR[T][0], r1 = c_dstR[T][1], r2 = c_dstR[T][2];
    float* out = out_base + (size_t)T*NH;

    int d    = (blockIdx.x*blockDim.x + threadIdx.x) >> 5;
    int lane = threadIdx.x & 31;
    if (d >= NN) return;
    const int c = lane*4;

    float4 res;
    {
        float4 b0 = *(const float4*)&bc[r0*128 + c];
        float4 b1 = *(const float4*)&bc[r1*128 + c];
        float4 b2 = *(const float4*)&bc[r2*128 + c];
        res.x = b0.x + b1.x + b2.x;
        res.y = b0.y + b1.y + b2.y;
        res.z = b0.z + b1.z + b2.z;
        res.w = b0.w + b1.w + b2.w;
    }

    int rels[3]; rels[0] = r0; rels[1] = r1; rels[2] = r2;
    #pragma unroll
    for (int i = 0; i < 3; i++){
        const int r = rels[i];
        const int* off = off9 + r*(NN+1);
        const int* es  = esrc9 + (size_t)r*EE;
        const float* GL = GLa + (size_t)r*NH;
        float4 gr = *(const float4*)&GRa[(size_t)r*NH + (size_t)d*128 + c];
        float4 at = *(const float4*)&att[r*128 + c];
        int beg = off[d], end = off[d+1];
        float m = -INFINITY, den = 0.f;
        float4 acc = make_float4(0.f,0.f,0.f,0.f);
        if (beg < end){
            int s0 = es[beg];
            float4 gl = *(const float4*)&GL[(size_t)s0*128 + c];
            for (int k = beg; k < end; k++){
                int kn = (k + 1 < end) ? (k + 1) : k;
                int sn = es[kn];
                float4 gln = *(const float4*)&GL[(size_t)sn*128 + c];

                float sx = gl.x + gr.x, sy = gl.y + gr.y, sz = gl.z + gr.z, sw = gl.w + gr.w;
                sx = sx > 0.f ? sx : 0.2f*sx;
                sy = sy > 0.f ? sy : 0.2f*sy;
                sz = sz > 0.f ? sz : 0.2f*sz;
                sw = sw > 0.f ? sw : 0.2f*sw;
                float e = at.x*sx + at.y*sy + at.z*sz + at.w*sw;
                e += __shfl_xor_sync(0xffffffffu, e, 1);
                e += __shfl_xor_sync(0xffffffffu, e, 2);
                e += __shfl_xor_sync(0xffffffffu, e, 4);
                e += __shfl_xor_sync(0xffffffffu, e, 8);   // per-head score per half-warp
                float mn = fmaxf(m, e);
                float cs = __expf(m - mn);
                float p  = __expf(e - mn);
                den = den*cs + p;
                acc.x = acc.x*cs + p*gl.x;
                acc.y = acc.y*cs + p*gl.y;
                acc.z = acc.z*cs + p*gl.z;
                acc.w = acc.w*cs + p*gl.w;
                m = mn;
                gl = gln;
            }
        }
        float inv = 1.f / (den + 1e-16f);
        res.x += acc.x*inv;
        res.y += acc.y*inv;
        res.z += acc.z*inv;
        res.w += acc.w*inv;
    }
    if (dorelu){
        res.x = fmaxf(res.x, 0.f); res.y = fmaxf(res.y, 0.f);
        res.z = fmaxf(res.z, 0.f); res.w = fmaxf(res.w, 0.f);
    }
    *(float4*)&out[(size_t)d*128 + c] = res;
}

// ---------------- launch ----------------
extern "C" void kernel_launch(void* const* d_in, const int* in_sizes, int n_in,
                              void* d_out, int out_size){
    float *h, *GLa, *GRa, *Wc, *brow;
    __half *Whf;
    int *off9, *esrc9, *cnt9, *bsum9;
    cudaGetSymbolAddress((void**)&h,     g_h);
    cudaGetSymbolAddress((void**)&GLa,   g_GLa);
    cudaGetSymbolAddress((void**)&GRa,   g_GRa);
    cudaGetSymbolAddress((void**)&Wc,    g_Wc);
    cudaGetSymbolAddress((void**)&brow,  g_brow);
    cudaGetSymbolAddress((void**)&Whf,   g_Whf);
    cudaGetSymbolAddress((void**)&off9,  g_off9);
    cudaGetSymbolAddress((void**)&esrc9, g_esrc9);
    cudaGetSymbolAddress((void**)&cnt9,  g_cnt9);
    cudaGetSymbolAddress((void**)&bsum9, g_bsum9);

    cudaFuncSetAttribute(k_gemm6, cudaFuncAttributeMaxDynamicSharedMemorySize, G_TOTAL);
    cudaFuncSetAttribute(k_p16,   cudaFuncAttributeMaxDynamicSharedMemorySize, P_TOTAL);

    EI9 ei;
    for (int r = 0; r < 9; r++) ei.p[r] = (const int*)d_in[3 + r];
    X3 xs;
    xs.p[0] = (const float*)d_in[0];
    xs.p[1] = (const float*)d_in[1];
    xs.p[2] = (const float*)d_in[2];
    WB3 wb;
    wb.W[0] = (const float*)d_in[12]; wb.b[0] = (const float*)d_in[13];
    wb.W[1] = (const float*)d_in[14]; wb.b[1] = (const float*)d_in[15];
    wb.W[2] = (const float*)d_in[16]; wb.b[2] = (const float*)d_in[17];

    const int gblk = (NN + 127) / 128;
    float* outF = (float*)d_out;

    // CSR build + layer-1 projections + weight pre-conversion
    k_zero<<<(9*NN + 255)/256, 256>>>(cnt9, 9*NN);
    { dim3 g((EE+255)/256, 9);   k_hist9  <<<g, 256>>> (ei, cnt9); }
    { dim3 g(9, 2); k_precomp<<<g, 128>>>(wb, (const float*)d_in[18], (const float*)d_in[19], Wc, brow); }
    { dim3 g(9, 2); k_wconv  <<<g, 256>>>((const float*)d_in[22], (const float*)d_in[23], Whf); }
    { dim3 g(gblk, 3); k_p16<<<g, 256, P_TOTAL>>>(xs, Wc, brow, GLa, GRa); }
    { dim3 g((NN+1023)/1024, 9); k_scan1_9<<<g, 1024>>>(cnt9, off9, bsum9); }
    { dim3 g((NN+1023)/1024, 9); k_scan2_9<<<g, 1024>>>(off9, bsum9); }
    { dim3 g((EE+255)/256, 9);   k_fill9  <<<g, 256>>> (ei, off9, cnt9, esrc9); }
    // layer-1 GAT (+bias +relu) -> h   (batched over dst types)
    { dim3 g(NN/8, 3);
      k_gat3<<<g, 256>>>(off9, esrc9, GLa, GRa,
                         (const float*)d_in[20], (const float*)d_in[21], h, 1); }
    // layer-2 projections (fp16 2-term, single-buffered B, occ 2)
    { dim3 g(gblk, 3); k_gemm6<<<g, 256, G_TOTAL>>>(h, Whf, GLa, GRa); }
    // layer-2 GAT (+bias) -> output  (batched over dst types)
    { dim3 g(NN/8, 3);
      k_gat3<<<g, 256>>>(off9, esrc9, GLa, GRa,
                         (const float*)d_in[24], (const float*)d_in[25], outF, 0); }
}

// round 15
// speedup vs baseline: 1.3985x; 1.0215x over previous
#include <cuda_runtime.h>
#include <cuda_bf16.h>
#include <cuda_fp16.h>
#include <cstdint>
#include <math.h>

typedef unsigned int       u32;
typedef unsigned long long u64;

#define NN 100000
#define EE 300000
#define HIDD 128
#define NH (NN*HIDD)

// ---------------- static scratch (no allocations allowed) ----------------
__device__ float  g_h[3*NH];        // layer-1 GAT output (t,v,e) = layer-2 input
__device__ float  g_GLa[9*NH];      // per-relation src projections
__device__ float  g_GRa[9*NH];      // per-relation dst projections
__device__ float  g_Wc[2*9*16*128]; // combined layer-1 weights  [side][rel][16][128]
__device__ float  g_brow[2*9*128];  // combined layer-1 bias rows
__device__ __half g_Whf[18*17408];  // layer-2 weights, padded fp16 images
__device__ int    g_off9[9*(NN+1)];
__device__ int    g_esrc9[9*EE];
__device__ int    g_cnt9[9*NN];
__device__ int    g_bsum9[9*128];

struct EI9 { const int* p[9]; };
struct X3  { const float* p[3]; };
struct WB3 { const float* W[3]; const float* b[3]; };

__device__ __constant__ int c_srct[9] = {0,0,1,0,2,1,2,1,2};
__device__ __constant__ int c_dstt[9] = {0,1,0,2,0,2,1,1,2};
__device__ __constant__ int c_dstR[3][3] = {{0,2,4},{1,6,7},{3,5,8}};

// ================= baseline-PTX helpers =================
__device__ __forceinline__ u32 smem_u32(const void* p){
    u32 a;
    asm("{ .reg .u64 t; cvta.to.shared.u64 t, %1; cvt.u32.u64 %0, t; }" : "=r"(a) : "l"(p));
    return a;
}
__device__ __forceinline__ void ldsm4(u32* r, u32 addr){
    asm volatile("ldmatrix.sync.aligned.m8n8.x4.shared.b16 {%0,%1,%2,%3}, [%4];"
        : "=r"(r[0]),"=r"(r[1]),"=r"(r[2]),"=r"(r[3]) : "r"(addr));
}
__device__ __forceinline__ void ldsm2t(u32* r, u32 addr){
    asm volatile("ldmatrix.sync.aligned.m8n8.x2.trans.shared.b16 {%0,%1}, [%2];"
        : "=r"(r[0]),"=r"(r[1]) : "r"(addr));
}
__device__ __forceinline__ void mma16816(float* d, const u32* a, const u32* b){
    asm volatile(
        "mma.sync.aligned.m16n8k16.row.col.f32.bf16.bf16.f32 "
        "{%0,%1,%2,%3}, {%4,%5,%6,%7}, {%8,%9}, {%0,%1,%2,%3};"
        : "+f"(d[0]),"+f"(d[1]),"+f"(d[2]),"+f"(d[3])
        : "r"(a[0]),"r"(a[1]),"r"(a[2]),"r"(a[3]), "r"(b[0]),"r"(b[1]));
}
__device__ __forceinline__ void mma16816h(float* d, const u32* a, const u32* b){
    asm volatile(
        "mma.sync.aligned.m16n8k16.row.col.f32.f16.f16.f32 "
        "{%0,%1,%2,%3}, {%4,%5,%6,%7}, {%8,%9}, {%0,%1,%2,%3};"
        : "+f"(d[0]),"+f"(d[1]),"+f"(d[2]),"+f"(d[3])
        : "r"(a[0]),"r"(a[1]),"r"(a[2]),"r"(a[3]), "r"(b[0]),"r"(b[1]));
}
__device__ __forceinline__ void bf_split(float x, __nv_bfloat16& hi, __nv_bfloat16& lo){
    hi = __float2bfloat16(x);
    lo = __float2bfloat16(x - __bfloat162float(hi));
}
__device__ __forceinline__ void hf_split(float x, __half& hi, __half& lo){
    hi = __float2half(x);
    lo = __float2half(x - __half2float(hi));
}
__device__ __forceinline__ void cp16(u32 dst, const void* src){
    asm volatile("cp.async.cg.shared.global [%0], [%1], 16;" :: "r"(dst), "l"(src));
}

// ======== layer-2 GEMM smem layout (A fp16 hi/lo + single fp16 B buffer -> occ 2) ========
#define LDE 136
#define PLANE 34816                 // 128*136*2 bytes
#define G_AHI 0
#define G_ALO PLANE
#define G_BB  (2*PLANE)
#define G_TOTAL (3*PLANE)           // 104448 -> 2 CTAs/SM

// ======== layer-1 skinny GEMM smem layout (K=16, 6 weights, bf16 3-term) ========
#define LDA16 24
#define P_AHI 0
#define P_ALO (128*LDA16*2)                       // 6144
#define P_B(w)   (2*128*LDA16*2 + (w)*8704)
#define P_BLO(w) (P_B(w) + 4352)
#define P_BIAS   (2*128*LDA16*2 + 6*8704)         // 64512
#define P_TOTAL  (P_BIAS + 6*128*4)               // 67584

// ---------------- precompute combined layer-1 weights ----------------
__global__ void k_precomp(WB3 wb, const float* __restrict__ Wl1,
                          const float* __restrict__ Wr1,
                          float* __restrict__ Wc, float* __restrict__ brow){
    __shared__ float Ws[16*128];
    __shared__ float bs[128];
    const int rel  = blockIdx.x;
    const int side = blockIdx.y;
    const int ty   = side ? c_dstt[rel] : c_srct[rel];
    const float* Win = wb.W[ty];
    const float* bin = wb.b[ty];
    const float* WL  = (side ? Wr1 : Wl1) + (size_t)rel*16384;
    const int j = threadIdx.x;
    for (int i = j; i < 16*128; i += 128) Ws[i] = Win[i];
    bs[j] = bin[j];
    __syncthreads();
    float acc[16];
    #pragma unroll
    for (int i = 0; i < 16; i++) acc[i] = 0.f;
    float accb = 0.f;
    for (int k = 0; k < 128; k++){
        float wl = WL[k*128 + j];
        accb += bs[k]*wl;
        #pragma unroll
        for (int i = 0; i < 16; i++) acc[i] += Ws[i*128 + k]*wl;
    }
    float* Wcp = Wc + (size_t)(side*9 + rel)*2048;
    #pragma unroll
    for (int i = 0; i < 16; i++) Wcp[i*128 + j] = acc[i];
    brow[(side*9 + rel)*128 + j] = accb;
}

// ---------------- pre-convert layer-2 weights to padded fp16 images ----------
__global__ void k_wconv(const float* __restrict__ Wl, const float* __restrict__ Wr,
                        __half* __restrict__ out){
    const int rel  = blockIdx.x;
    const int side = blockIdx.y;
    const float* W = (side ? Wr : Wl) + (size_t)rel*16384;
    __half* base = out + (size_t)(side*9 + rel)*17408;
    for (int i = threadIdx.x; i < 16384; i += 256){
        int k = i >> 7, j = i & 127;
        base[k*LDE + j] = __float2half(W[i]);
    }
}

// ---------------- layer-1 projections: GL/GR = x[1e5,16] @ Wc[16,128] + brow ----------
__global__ __launch_bounds__(256, 2)
void k_p16(X3 xs, const float* __restrict__ Wc, const float* __restrict__ brow,
           float* __restrict__ GLa, float* __restrict__ GRa){
    static const int srcR[3][3] = {{0,1,3},{2,5,7},{4,6,8}};
    static const int dstR[3][3] = {{0,2,4},{1,6,7},{3,5,8}};
    extern __shared__ char smem[];
    float* bias_s = (float*)(smem + P_BIAS);
    const u32 sb = smem_u32(smem);
    const int tid  = threadIdx.x;
    const int wid  = tid >> 5;
    const int lane = tid & 31;
    const int T    = blockIdx.y;

    if (tid < 128){
        int rg = blockIdx.x*128 + tid;
        if (rg > NN-1) rg = NN-1;
        const float4* xp = (const float4*)(xs.p[T] + (size_t)rg*16);
        #pragma unroll
        for (int jj = 0; jj < 4; jj++){
            float4 v = xp[jj];
            __nv_bfloat16 h0,h1,h2,h3,l0,l1,l2,l3;
            bf_split(v.x,h0,l0); bf_split(v.y,h1,l1);
            bf_split(v.z,h2,l2); bf_split(v.w,h3,l3);
            __nv_bfloat162 ph0; ph0.x=h0; ph0.y=h1;
            __nv_bfloat162 ph1; ph1.x=h2; ph1.y=h3;
            __nv_bfloat162 pl0; pl0.x=l0; pl0.y=l1;
            __nv_bfloat162 pl1; pl1.x=l2; pl1.y=l3;
            u32 o = (u32)(tid*LDA16 + jj*4)*2;
            *(__nv_bfloat162*)(smem + P_AHI + o)     = ph0;
            *(__nv_bfloat162*)(smem + P_AHI + o + 4) = ph1;
            *(__nv_bfloat162*)(smem + P_ALO + o)     = pl0;
            *(__nv_bfloat162*)(smem + P_ALO + o + 4) = pl1;
        }
    }
    for (int idx = tid; idx < 6*512; idx += 256){
        int w = idx >> 9, rem = idx & 511;
        int k = rem >> 5, j = (rem & 31) << 2;
        int side = (w < 3) ? 0 : 1;
        int rel  = (w < 3) ? srcR[T][w] : dstR[T][w-3];
        float4 v = *(const float4*)(Wc + (size_t)(side*9+rel)*2048 + k*128 + j);
        __nv_bfloat16 h0,h1,h2,h3,l0,l1,l2,l3;
        bf_split(v.x,h0,l0); bf_split(v.y,h1,l1);
        bf_split(v.z,h2,l2); bf_split(v.w,h3,l3);
        __nv_bfloat162 ph0; ph0.x=h0; ph0.y=h1;
        __nv_bfloat162 ph1; ph1.x=h2; ph1.y=h3;
        __nv_bfloat162 pl0; pl0.x=l0; pl0.y=l1;
        __nv_bfloat162 pl1; pl1.x=l2; pl1.y=l3;
        u32 o = (u32)(k*LDE + j)*2;
        *(__nv_bfloat162*)(smem + P_B(w) + o)       = ph0;
        *(__nv_bfloat162*)(smem + P_B(w) + o + 4)   = ph1;
        *(__nv_bfloat162*)(smem + P_BLO(w) + o)     = pl0;
        *(__nv_bfloat162*)(smem + P_BLO(w) + o + 4) = pl1;
    }
    for (int idx = tid; idx < 6*128; idx += 256){
        int w = idx >> 7, c = idx & 127;
        int side = (w < 3) ? 0 : 1;
        int rel  = (w < 3) ? srcR[T][w] : dstR[T][w-3];
        bias_s[idx] = brow[(side*9+rel)*128 + c];
    }
    __syncthreads();

    const int mg = (wid >> 1) * 32;
    const int ng = (wid & 1) * 64;
    const int arow = mg + (lane & 15);
    const int acol = (lane >> 4) << 3;
    const int brw  = lane & 15;

    u32 a_hi[2][4], a_lo[2][4];
    #pragma unroll
    for (int mt = 0; mt < 2; mt++){
        u32 ao = (u32)((arow + mt*16)*LDA16 + acol)*2;
        ldsm4(a_hi[mt], sb + P_AHI + ao);
        ldsm4(a_lo[mt], sb + P_ALO + ao);
    }

    const int r0 = blockIdx.x*128 + mg + (lane >> 2);
    const int c0 = ng + ((lane & 3) << 1);

    #pragma unroll
    for (int w = 0; w < 6; w++){
        int side = (w < 3) ? 0 : 1;
        int rel  = (w < 3) ? srcR[T][w] : dstR[T][w-3];
        float* Cp = (side ? GRa : GLa) + (size_t)rel*NH;
        float acc[2][8][4];
        #pragma unroll
        for (int mt = 0; mt < 2; mt++)
            #pragma unroll
            for (int nt = 0; nt < 8; nt++)
                #pragma unroll
                for (int q = 0; q < 4; q++) acc[mt][nt][q] = 0.f;
        #pragma unroll
        for (int nt = 0; nt < 8; nt++){
            u32 bo = (u32)(brw*LDE + ng + nt*8)*2;
            u32 b_hi[2], b_lo[2];
            ldsm2t(b_hi, sb + P_B(w) + bo);
            ldsm2t(b_lo, sb + P_BLO(w) + bo);
            #pragma unroll
            for (int mt = 0; mt < 2; mt++){
                mma16816(acc[mt][nt], a_hi[mt], b_hi);
                mma16816(acc[mt][nt], a_lo[mt], b_hi);
                mma16816(acc[mt][nt], a_hi[mt], b_lo);
            }
        }
        #pragma unroll
        for (int mt = 0; mt < 2; mt++){
            #pragma unroll
            for (int nt = 0; nt < 8; nt++){
                int ra = r0 + mt*16;
                int cc = c0 + nt*8;
                float b0 = bias_s[w*128 + cc];
                float b1 = bias_s[w*128 + cc + 1];
                if (ra < NN){
                    float2 v0; v0.x = acc[mt][nt][0] + b0; v0.y = acc[mt][nt][1] + b1;
                    *(float2*)(Cp + (size_t)ra*128 + cc) = v0;
                }
                if (ra + 8 < NN){
                    float2 v1; v1.x = acc[mt][nt][2] + b0; v1.y = acc[mt][nt][3] + b1;
                    *(float2*)(Cp + (size_t)(ra+8)*128 + cc) = v1;
                }
            }
        }
    }
}

// ========== layer-2 multi-W GEMM: fp16 2-term, occ 2, copy overlapped with epilogue ==========
__global__ __launch_bounds__(256, 2)
void k_gemm6(const float* __restrict__ hbase, const __half* __restrict__ Whf,
             float* __restrict__ GLa, float* __restrict__ GRa){
    static const int srcR[3][3] = {{0,1,3},{2,5,7},{4,6,8}};
    static const int dstR[3][3] = {{0,2,4},{1,6,7},{3,5,8}};
    extern __shared__ char smem[];
    const u32 sb = smem_u32(smem);
    const int tid  = threadIdx.x;
    const int wid  = tid >> 5;
    const int lane = tid & 31;
    const int T    = blockIdx.y;
    const float* A = hbase + (size_t)T*NH;

    int rels[6];
    #pragma unroll
    for (int w = 0; w < 3; w++){ rels[w] = srcR[T][w]; rels[w+3] = dstR[T][w]; }

    auto copyW = [&](int w){
        int side = (w < 3) ? 0 : 1;
        const char* src = (const char*)(Whf + (size_t)(side*9 + rels[w])*17408);
        u32 dst = sb + G_BB;
        for (int i = tid*16; i < PLANE; i += 256*16)
            cp16(dst + i, src + i);
    };

    copyW(0);
    asm volatile("cp.async.commit_group;" ::: "memory");

    // ---- A tile fp16 hi/lo, converted once, reused by all 6 weights ----
    for (int idx = tid; idx < 128*32; idx += 256){
        int r = idx >> 5, j = (idx & 31) << 2;
        int rg = blockIdx.x*128 + r;
        if (rg > NN-1) rg = NN-1;
        float4 v = *(const float4*)(A + (size_t)rg*128 + j);
        __half h0,h1,h2,h3,l0,l1,l2,l3;
        hf_split(v.x,h0,l0); hf_split(v.y,h1,l1);
        hf_split(v.z,h2,l2); hf_split(v.w,h3,l3);
        __half2 ph0; ph0.x=h0; ph0.y=h1;
        __half2 ph1; ph1.x=h2; ph1.y=h3;
        __half2 pl0; pl0.x=l0; pl0.y=l1;
        __half2 pl1; pl1.x=l2; pl1.y=l3;
        u32 o = (u32)(r*LDE + j)*2;
        *(__half2*)(smem + G_AHI + o)     = ph0;
        *(__half2*)(smem + G_AHI + o + 4) = ph1;
        *(__half2*)(smem + G_ALO + o)     = pl0;
        *(__half2*)(smem + G_ALO + o + 4) = pl1;
    }

    const int mg = (wid >> 1) * 32;
    const int ng = (wid & 1) * 64;
    const int arow = mg + (lane & 15);
    const int acol = (lane >> 4) << 3;
    const int brow = lane & 15;
    const int r0g = blockIdx.x*128 + mg + (lane >> 2);
    const int c0 = ng + ((lane & 3) << 1);

    for (int w = 0; w < 6; w++){
        asm volatile("cp.async.wait_group 0;" ::: "memory");
        __syncthreads();    // B(w) ready for all warps (A visible on first iter)

        const u32 bhi = sb + G_BB;
        float* Cp = ((w < 3) ? GLa : GRa) + (size_t)rels[w]*NH;

        float acc[2][8][4];
        #pragma unroll
        for (int mt = 0; mt < 2; mt++)
            #pragma unroll
            for (int nt = 0; nt < 8; nt++)
                #pragma unroll
                for (int q = 0; q < 4; q++) acc[mt][nt][q] = 0.f;

        #pragma unroll
        for (int ks = 0; ks < 8; ks++){
            const int k0 = ks << 4;
            u32 a_hi[2][4], a_lo[2][4];
            #pragma unroll
            for (int mt = 0; mt < 2; mt++){
                u32 ao = (u32)((arow + mt*16)*LDE + k0 + acol)*2;
                ldsm4(a_hi[mt], sb + G_AHI + ao);
                ldsm4(a_lo[mt], sb + G_ALO + ao);
            }
            #pragma unroll
            for (int nt = 0; nt < 8; nt++){
                u32 bo = (u32)((k0 + brow)*LDE + ng + nt*8)*2;
                u32 b_hi[2];
                ldsm2t(b_hi, bhi + bo);
                #pragma unroll
                for (int mt = 0; mt < 2; mt++){
                    mma16816h(acc[mt][nt], a_hi[mt], b_hi);
                    mma16816h(acc[mt][nt], a_lo[mt], b_hi);
                }
            }
        }

        __syncthreads();    // all warps finished reading B(w)
        if (w < 5){
            copyW(w+1);     // overlap next weight's copy with the epilogue stores
            asm volatile("cp.async.commit_group;" ::: "memory");
        }

        #pragma unroll
        for (int mt = 0; mt < 2; mt++){
            #pragma unroll
            for (int nt = 0; nt < 8; nt++){
                int ra = r0g + mt*16;
                int cc = c0 + nt*8;
                if (ra < NN){
                    float2 v0; v0.x = acc[mt][nt][0]; v0.y = acc[mt][nt][1];
                    *(float2*)(Cp + (size_t)ra*128 + cc) = v0;
                }
                if (ra + 8 < NN){
                    float2 v1; v1.x = acc[mt][nt][2]; v1.y = acc[mt][nt][3];
                    *(float2*)(Cp + (size_t)(ra+8)*128 + cc) = v1;
                }
            }
        }
    }
}

// ---------------- batched CSR build ----------------
__global__ void k_zero(int* p, int n){
    int i = blockIdx.x*blockDim.x + threadIdx.x;
    if (i < n) p[i] = 0;
}
__global__ void k_hist9(EI9 ei, int* __restrict__ cnt9){
    int z = blockIdx.y;
    int e = blockIdx.x*blockDim.x + threadIdx.x;
    if (e < EE) atomicAdd(&cnt9[z*NN + ei.p[z][EE + e]], 1);
}
__global__ void k_scan1_9(int* __restrict__ cnt9, int* __restrict__ off9,
                          int* __restrict__ bsum9){
    __shared__ int sh[1024];
    int z = blockIdx.y;
    int d = blockIdx.x*1024 + threadIdx.x;
    sh[threadIdx.x] = (d < NN) ? cnt9[z*NN + d] : 0;
    if (d < NN) cnt9[z*NN + d] = 0;
    __syncthreads();
    for (int s = 1; s < 1024; s <<= 1){
        int t = (threadIdx.x >= s) ? sh[threadIdx.x - s] : 0;
        __syncthreads();
        sh[threadIdx.x] += t;
        __syncthreads();
    }
    if (d < NN) off9[z*(NN+1) + d + 1] = sh[threadIdx.x];
    if (threadIdx.x == 1023) bsum9[z*128 + blockIdx.x] = sh[1023];
}
__global__ void k_scan2_9(int* __restrict__ off9, const int* __restrict__ bsum9){
    __shared__ int pre;
    int z = blockIdx.y;
    if (threadIdx.x == 0){
        int s = 0;
        for (int b = 0; b < (int)blockIdx.x; b++) s += bsum9[z*128 + b];
        pre = s;
    }
    __syncthreads();
    int d = blockIdx.x*1024 + threadIdx.x;
    if (d < NN) off9[z*(NN+1) + d + 1] += pre;
    if (d == 0) off9[z*(NN+1)] = 0;
}
__global__ void k_fill9(EI9 ei, const int* __restrict__ off9,
                        int* __restrict__ cnt9, int* __restrict__ esrc9){
    int z = blockIdx.y;
    int e = blockIdx.x*blockDim.x + threadIdx.x;
    if (e < EE){
        int d = ei.p[z][EE + e];
        int pos = off9[z*(NN+1) + d] + atomicAdd(&cnt9[z*NN + d], 1);
        esrc9[z*EE + pos] = ei.p[z][e];
    }
}

// ---------------- fused GATv2: grid.y = dst type, depth-2 prefetch ----------
__global__ __launch_bounds__(256)
void k_gat3(const int* __restrict__ off9, const int* __restrict__ esrc9,
            const float* __restrict__ GLa, const float* __restrict__ GRa,
            const float* __restrict__ att, const float* __restrict__ bc,
            float* __restrict__ out_base, int dorelu){
    const int T = blockIdx.y;
    const int r0 = c_dstR[T][0], r1 = c_dstR[T][1], r2 = c_dstR[T][2];
    float* out = out_base + (size_t)T*NH;

    int d    = (blockIdx.x*blockDim.x + threadIdx.x) >> 5;
    int lane = threadIdx.x & 31;
    if (d >= NN) return;
    const int c = lane*4;

    float4 res;
    {
        float4 b0 = *(const float4*)&bc[r0*128 + c];
        float4 b1 = *(const float4*)&bc[r1*128 + c];
        float4 b2 = *(const float4*)&bc[r2*128 + c];
        res.x = b0.x + b1.x + b2.x;
        res.y = b0.y + b1.y + b2.y;
        res.z = b0.z + b1.z + b2.z;
        res.w = b0.w + b1.w + b2.w;
    }

    int rels[3]; rels[0] = r0; rels[1] = r1; rels[2] = r2;
    #pragma unroll
    for (int i = 0; i < 3; i++){
        const int r = rels[i];
        const int* off = off9 + r*(NN+1);
        const int* es  = esrc9 + (size_t)r*EE;
        const float* GL = GLa + (size_t)r*NH;
        float4 gr = *(const float4*)&GRa[(size_t)r*NH + (size_t)d*128 + c];
        float4 at = *(const float4*)&att[r*128 + c];
        int beg = off[d], end = off[d+1];
        float m = -INFINITY, den = 0.f;
        float4 acc = make_float4(0.f,0.f,0.f,0.f);
        if (beg < end){
            int s0 = es[beg];
            float4 gl = *(const float4*)&GL[(size_t)s0*128 + c];
            for (int k = beg; k < end; k++){
                int kn = (k + 1 < end) ? (k + 1) : k;
                int sn = es[kn];
                float4 gln = *(const float4*)&GL[(size_t)sn*128 + c];

                float sx = gl.x + gr.x, sy = gl.y + gr.y, sz = gl.z + gr.z, sw = gl.w + gr.w;
                sx = sx > 0.f ? sx : 0.2f*sx;
                sy = sy > 0.f ? sy : 0.2f*sy;
                sz = sz > 0.f ? sz : 0.2f*sz;
                sw = sw > 0.f ? sw : 0.2f*sw;
                float e = at.x*sx + at.y*sy + at.z*sz + at.w*sw;
                e += __shfl_xor_sync(0xffffffffu, e, 1);
                e += __shfl_xor_sync(0xffffffffu, e, 2);
                e += __shfl_xor_sync(0xffffffffu, e, 4);
                e += __shfl_xor_sync(0xffffffffu, e, 8);   // per-head score per half-warp
                float mn = fmaxf(m, e);
                float cs = __expf(m - mn);
                float p  = __expf(e - mn);
                den = den*cs + p;
                acc.x = acc.x*cs + p*gl.x;
                acc.y = acc.y*cs + p*gl.y;
                acc.z = acc.z*cs + p*gl.z;
                acc.w = acc.w*cs + p*gl.w;
                m = mn;
                gl = gln;
            }
        }
        float inv = 1.f / (den + 1e-16f);
        res.x += acc.x*inv;
        res.y += acc.y*inv;
        res.z += acc.z*inv;
        res.w += acc.w*inv;
    }
    if (dorelu){
        res.x = fmaxf(res.x, 0.f); res.y = fmaxf(res.y, 0.f);
        res.z = fmaxf(res.z, 0.f); res.w = fmaxf(res.w, 0.f);
    }
    *(float4*)&out[(size_t)d*128 + c] = res;
}

// ---------------- launch ----------------
extern "C" void kernel_launch(void* const* d_in, const int* in_sizes, int n_in,
                              void* d_out, int out_size){
    float *h, *GLa, *GRa, *Wc, *brow;
    __half *Whf;
    int *off9, *esrc9, *cnt9, *bsum9;
    cudaGetSymbolAddress((void**)&h,     g_h);
    cudaGetSymbolAddress((void**)&GLa,   g_GLa);
    cudaGetSymbolAddress((void**)&GRa,   g_GRa);
    cudaGetSymbolAddress((void**)&Wc,    g_Wc);
    cudaGetSymbolAddress((void**)&brow,  g_brow);
    cudaGetSymbolAddress((void**)&Whf,   g_Whf);
    cudaGetSymbolAddress((void**)&off9,  g_off9);
    cudaGetSymbolAddress((void**)&esrc9, g_esrc9);
    cudaGetSymbolAddress((void**)&cnt9,  g_cnt9);
    cudaGetSymbolAddress((void**)&bsum9, g_bsum9);

    cudaFuncSetAttribute(k_gemm6, cudaFuncAttributeMaxDynamicSharedMemorySize, G_TOTAL);
    cudaFuncSetAttribute(k_p16,   cudaFuncAttributeMaxDynamicSharedMemorySize, P_TOTAL);

    EI9 ei;
    for (int r = 0; r < 9; r++) ei.p[r] = (const int*)d_in[3 + r];
    X3 xs;
    xs.p[0] = (const float*)d_in[0];
    xs.p[1] = (const float*)d_in[1];
    xs.p[2] = (const float*)d_in[2];
    WB3 wb;
    wb.W[0] = (const float*)d_in[12]; wb.b[0] = (const float*)d_in[13];
    wb.W[1] = (const float*)d_in[14]; wb.b[1] = (const float*)d_in[15];
    wb.W[2] = (const float*)d_in[16]; wb.b[2] = (const float*)d_in[17];

    const int gblk = (NN + 127) / 128;
    float* outF = (float*)d_out;

    // CSR build + layer-1 projections + weight pre-conversion
    k_zero<<<(9*NN + 255)/256, 256>>>(cnt9, 9*NN);
    { dim3 g((EE+255)/256, 9);   k_hist9  <<<g, 256>>> (ei, cnt9); }
    { dim3 g(9, 2); k_precomp<<<g, 128>>>(wb, (const float*)d_in[18], (const float*)d_in[19], Wc, brow); }
    { dim3 g(9, 2); k_wconv  <<<g, 256>>>((const float*)d_in[22], (const float*)d_in[23], Whf); }
    { dim3 g(gblk, 3); k_p16<<<g, 256, P_TOTAL>>>(xs, Wc, brow, GLa, GRa); }
    { dim3 g((NN+1023)/1024, 9); k_scan1_9<<<g, 1024>>>(cnt9, off9, bsum9); }
    { dim3 g((NN+1023)/1024, 9); k_scan2_9<<<g, 1024>>>(off9, bsum9); }
    { dim3 g((EE+255)/256, 9);   k_fill9  <<<g, 256>>> (ei, off9, cnt9, esrc9); }
    // layer-1 GAT (+bias +relu) -> h   (batched over dst types)
    { dim3 g(NN/8, 3);
      k_gat3<<<g, 256>>>(off9, esrc9, GLa, GRa,
                         (const float*)d_in[20], (const float*)d_in[21], h, 1); }
    // layer-2 projections (fp16 2-term, occ 2, copy/epilogue overlap)
    { dim3 g(gblk, 3); k_gemm6<<<g, 256, G_TOTAL>>>(h, Whf, GLa, GRa); }
    // layer-2 GAT (+bias) -> output  (batched over dst types)
    { dim3 g(NN/8, 3);
      k_gat3<<<g, 256>>>(off9, esrc9, GLa, GRa,
                         (const float*)d_in[24], (const float*)d_in[25], outF, 0); }
}